// round 6
// baseline (speedup 1.0000x reference)
#include <cuda_runtime.h>
#include <cuda_bf16.h>
#include <math.h>

#define BB 8
#define NN 96
#define DD 16
#define H0 50
#define H1 50
#define OUTD 64
#define SLOPE 0.05f
#define NTH 256

__device__ __forceinline__ float leaky(float v) { return v >= 0.f ? v : SLOPE * v; }

__global__ void __launch_bounds__(NTH) sgc_one(
    const float* __restrict__ x, const float* __restrict__ adj,
    const float* __restrict__ W1, const float* __restrict__ b1,
    const float* __restrict__ W2, const float* __restrict__ b2,
    const float* __restrict__ W3, const float* __restrict__ b3,
    float* __restrict__ out)
{
    const int tid = threadIdx.x;
    const int w = tid >> 5, lane = tid & 31;
    const int b  = blockIdx.x / (NN/2);
    const int i0 = (blockIdx.x % (NN/2)) * 2;

    __shared__ __align__(16) float xb[NN*17];        // 6528
    __shared__ __align__(16) float W1s[51*H0];       // 10200
    __shared__ __align__(16) float b1s[H0+2];
    __shared__ float b2s[H1+2], b3s[OUTD];
    __shared__ float adjIf[2*NN];                    // adj rows i0,i1
    __shared__ float disI[2*NN];
    __shared__ unsigned char nzI[2*NN];
    __shared__ int   wcnt[6];  __shared__ float part[6];
    __shared__ int   nnzI[2];  __shared__ float degIf[2], sdjkI[2];
    __shared__ float adjxI[2*DD];
    __shared__ float A_I[2*H0], taccS[2*H0], m2S[2*H1], base2S[2*H1], xw3S[2*OUTD];
    // chunk arrays: pair p = ii*32 + m
    __shared__ unsigned char nzJ[64*NN];             // 6144
    __shared__ int   cntJ[64], jof[64];
    __shared__ float degJ[64], sdjkU[64], sdikU[64], ddijU[64];
    __shared__ float adjxU[64*DD];                   // 4096
    __shared__ float PU[64*H0];                      // 12800

    // ---- Phase 1: front-batched independent loads ----
    {
        const float4* xv = (const float4*)(x + b*NN*DD);
        #pragma unroll
        for (int idx = tid; idx < NN*DD/4; idx += NTH) {
            float4 v = xv[idx];
            const int base = (idx >> 2)*17 + (idx & 3)*4;
            xb[base] = v.x; xb[base+1] = v.y; xb[base+2] = v.z; xb[base+3] = v.w;
        }
        const float2* w1v = (const float2*)W1;
        #pragma unroll
        for (int idx = tid; idx < 51*H0/2; idx += NTH) ((float2*)W1s)[idx] = w1v[idx];
        if (tid < H0) b1s[tid] = b1[tid];
        else if (tid < H0+H1) b2s[tid-H0] = b2[tid-H0];
        else if (tid < H0+H1+OUTD) b3s[tid-H0-H1] = b3[tid-H0-H1];
        if (tid < 2*NN) adjIf[tid] = adj[(b*NN + i0 + (tid >= NN))*NN + (tid % NN)];
    }
    __syncthreads();

    // ---- Phase 2: dis rows for i0,i1 + compaction + deg/sdjk ----
    bool nzb = false; unsigned mk = 0u; int kk = 0, iib = 0;
    if (tid < 2*NN) {       // warps 0..5 exactly
        iib = tid / NN; kk = tid % NN;
        const int i = i0 + iib;
        float d2 = 1e-10f;
        #pragma unroll
        for (int d = 0; d < DD; d++) { const float df = xb[i*17+d] - xb[kk*17+d]; d2 += df*df; }
        const float ds = sqrtf(d2);
        disI[tid] = ds;
        const float av = adjIf[tid];
        nzb = (av != 0.f);
        mk = __ballot_sync(~0u, nzb);
        float pv = av * ds;
        #pragma unroll
        for (int o = 16; o; o >>= 1) pv += __shfl_down_sync(~0u, pv, o);
        if (lane == 0) { wcnt[w] = __popc(mk); part[w] = pv; }
    }
    __syncthreads();
    if (tid < 2*NN && nzb) {
        const int wl = (tid % NN) / 32;
        int off = __popc(mk & ((1u << lane) - 1u));
        #pragma unroll
        for (int u = 0; u < 3; u++) if (u < wl) off += wcnt[iib*3 + u];
        nzI[iib*NN + off] = (unsigned char)kk;
    }
    if (tid < 2) {
        const int nn = wcnt[tid*3] + wcnt[tid*3+1] + wcnt[tid*3+2];
        nnzI[tid] = nn; degIf[tid] = (float)nn;
        sdjkI[tid] = part[tid*3] + part[tid*3+1] + part[tid*3+2];
    }
    __syncthreads();

    // ---- Phase 3: adjx_i, A_i, base2 (W2 direct), xw3 (W3 direct) ----
    if (tid < 2*DD) {
        const int ii = tid / DD, d = tid % DD;
        const int nn = nnzI[ii];
        float acc = 0.f;
        for (int m = 0; m < nn; m++) acc += xb[nzI[ii*NN + m]*17 + d];
        adjxI[tid] = acc;
    } else if (tid >= 32 && tid < 32 + 2*H0) {
        const int idx = tid - 32, ii = idx / H0, h = idx % H0;
        const int i = i0 + ii;
        float acc = 0.f;
        #pragma unroll
        for (int d = 0; d < DD; d++) acc = fmaf(xb[i*17+d], W1s[d*H0 + h], acc);
        A_I[idx] = acc;
    }
    __syncthreads();
    if (tid < 2*H1) {
        const int ii = tid / H1, h1 = tid % H1, i = i0 + ii;
        const float dgi = degIf[ii];
        float acc = dgi * b2s[h1];
        #pragma unroll
        for (int d = 0; d < DD; d++) {
            acc = fmaf(dgi * xb[i*17+d], W2[d*H1 + h1], acc);
            acc = fmaf(adjxI[ii*DD + d], W2[(DD + d)*H1 + h1], acc);
        }
        acc = fmaf(sdjkI[ii], W2[(2*DD)*H1 + h1], acc);
        base2S[tid] = acc;
    } else if (tid >= 128) {
        const int idx = tid - 128, ii = idx / OUTD, o = idx % OUTD, i = i0 + ii;
        float acc = b3s[o];
        #pragma unroll
        for (int d = 0; d < DD; d++) acc = fmaf(xb[i*17+d], W3[d*OUTD + o], acc);
        xw3S[idx] = acc;
    }

    // ---- Chunk loop over neighbors (32 per ii per round) ----
    float taccR = 0.f;
    const int ii_t = (tid < 2*H0) ? tid / H0 : 0;
    const int h_t  = (tid < 2*H0) ? tid % H0 : 0;
    const int maxnnz = max(nnzI[0], nnzI[1]);

    for (int c0 = 0; c0 < maxnnz; c0 += 32) {
        // dependent epoch: warp per pair loads adj row of neighbor j
        for (int p = w; p < 64; p += 8) {
            const int ii = p >> 5, m = p & 31;
            const bool act = (c0 + m) < nnzI[ii];
            const int j = act ? (int)nzI[ii*NN + c0 + m] : 0;
            const float* row = adj + (b*NN + j)*NN;
            float a0 = 0.f, a1 = 0.f, a2 = 0.f;
            if (act) { a0 = row[lane]; a1 = row[lane+32]; a2 = row[lane+64]; }
            const unsigned m0 = __ballot_sync(~0u, a0 != 0.f);
            const unsigned m1 = __ballot_sync(~0u, a1 != 0.f);
            const unsigned m2b = __ballot_sync(~0u, a2 != 0.f);
            const int c0n = __popc(m0), c1n = __popc(m1), c2n = __popc(m2b);
            const unsigned lt = (1u << lane) - 1u;
            unsigned char* nl = nzJ + p*NN;
            if (a0 != 0.f) nl[__popc(m0 & lt)]             = (unsigned char)lane;
            if (a1 != 0.f) nl[c0n + __popc(m1 & lt)]       = (unsigned char)(lane+32);
            if (a2 != 0.f) nl[c0n + c1n + __popc(m2b & lt)] = (unsigned char)(lane+64);
            if (lane == 0) {
                cntJ[p] = act ? (c0n + c1n + c2n) : 0;
                degJ[p] = (float)(c0n + c1n + c2n);
                jof[p]  = j;
            }
        }
        __syncthreads();

        // adjxU[p][d]
        #pragma unroll
        for (int idx = tid; idx < 64*DD; idx += NTH) {
            const int p = idx >> 4, d = idx & 15;
            const int cnt = cntJ[p];
            const unsigned char* nl = nzJ + p*NN;
            float acc = 0.f;
            for (int q = 0; q < cnt; q++) acc += xb[nl[q]*17 + d];
            adjxU[idx] = acc;
        }
        // sdjkU[p]: warp per p, dis(j,k) on the fly
        for (int p = w; p < 64; p += 8) {
            const int j = jof[p], cnt = cntJ[p];
            const unsigned char* nl = nzJ + p*NN;
            float acc = 0.f;
            for (int q = lane; q < cnt; q += 32) {
                const int k = nl[q];
                float d2 = 1e-10f;
                #pragma unroll
                for (int d = 0; d < DD; d++) { const float df = xb[j*17+d] - xb[k*17+d]; d2 += df*df; }
                acc += sqrtf(d2);
            }
            #pragma unroll
            for (int o = 16; o; o >>= 1) acc += __shfl_down_sync(~0u, acc, o);
            if (lane == 0) sdjkU[p] = acc;
        }
        // sdikU[p], ddijU[p]
        if (tid < 64) {
            const int p = tid, ii = p >> 5;
            const int cnt = cntJ[p];
            const unsigned char* nl = nzJ + p*NN;
            float acc = 0.f;
            for (int q = 0; q < cnt; q++) acc += disI[ii*NN + nl[q]];
            sdikU[p] = acc;
            ddijU[p] = degJ[p] * disI[ii*NN + jof[p]];
        }
        __syncthreads();

        // PU[p][h] (h-paired)
        #pragma unroll
        for (int idx = tid; idx < 64*(H0/2); idx += NTH) {
            const int p = idx / (H0/2), hp = idx % (H0/2), h = 2*hp;
            const int j = jof[p];
            float B0 = 0.f, B1 = 0.f, C0 = 0.f, C1 = 0.f;
            #pragma unroll
            for (int d = 0; d < DD; d++) {
                const float xv = xb[j*17 + d], av = adjxU[p*DD + d];
                const float2 wB = *(const float2*)&W1s[(DD   + d)*H0 + h];
                const float2 wC = *(const float2*)&W1s[(2*DD + d)*H0 + h];
                B0 = fmaf(xv, wB.x, B0); B1 = fmaf(xv, wB.y, B1);
                C0 = fmaf(av, wC.x, C0); C1 = fmaf(av, wC.y, C1);
            }
            const float dg = degJ[p], sj = sdjkU[p];
            const float2 wjk = *(const float2*)&W1s[(3*DD + 1)*H0 + h];
            const float2 bb  = *(const float2*)&b1s[h];
            PU[p*H0 + h]     = dg*(B0 + bb.x) + C0 + sj*wjk.x;
            PU[p*H0 + h + 1] = dg*(B1 + bb.y) + C1 + sj*wjk.y;
        }
        __syncthreads();

        // t accumulation
        if (tid < 2*H0) {
            const float Ah  = A_I[tid];
            const float wij = W1s[(3*DD)*H0 + h_t];
            const float wik = W1s[(3*DD + 2)*H0 + h_t];
            const int lim = nnzI[ii_t] - c0;
            const int mn = lim < 32 ? lim : 32;
            for (int m = 0; m < mn; m++) {
                const int p = ii_t*32 + m;
                const float Sv = fmaf(degJ[p], Ah,
                                 fmaf(ddijU[p], wij,
                                 fmaf(sdikU[p], wik, PU[p*H0 + h_t])));
                taccR += leaky(Sv);
            }
        }
        __syncthreads();
    }

    if (tid < 2*H0) taccS[tid] = taccR;
    __syncthreads();

    // ---- m2_sum ----
    if (tid < 2*H1) {
        const int ii = tid / H1, h1 = tid % H1;
        float acc = base2S[tid];
        #pragma unroll 10
        for (int h = 0; h < H0; h++)
            acc = fmaf(taccS[ii*H0 + h], W2[(2*DD + 1 + h)*H1 + h1], acc);
        m2S[tid] = leaky(acc);
    }
    __syncthreads();

    // ---- output ----
    if (tid < 2*OUTD) {
        const int ii = tid / OUTD, o = tid % OUTD;
        float acc = xw3S[tid];
        #pragma unroll 10
        for (int h = 0; h < H1; h++)
            acc = fmaf(m2S[ii*H1 + h], W3[(DD + h)*OUTD + o], acc);
        out[(b*NN + i0 + ii)*OUTD + o] = leaky(acc);
    }
}

extern "C" void kernel_launch(void* const* d_in, const int* in_sizes, int n_in,
                              void* d_out, int out_size)
{
    const float* x   = (const float*)d_in[0];
    const float* adj = (const float*)d_in[1];
    const float* W1  = (const float*)d_in[2];
    const float* b1  = (const float*)d_in[3];
    const float* W2  = (const float*)d_in[4];
    const float* b2  = (const float*)d_in[5];
    const float* W3  = (const float*)d_in[6];
    const float* b3  = (const float*)d_in[7];
    float* out = (float*)d_out;

    sgc_one<<<BB*(NN/2), NTH>>>(x, adj, W1, b1, W2, b2, W3, b3, out);
}

// round 8
// speedup vs baseline: 2.2571x; 2.2571x over previous
#include <cuda_runtime.h>
#include <cuda_bf16.h>
#include <math.h>

#define BB 8
#define NN 96
#define DD 16
#define H0 50
#define H1 50
#define OUTD 64
#define SLOPE 0.05f
#define CHUNK 32

// Scratch (__device__ globals; allocation-free)
__device__ float g_A[BB*NN*H0];
__device__ float g_P[BB*NN*H0];
__device__ float g_deg[BB*NN];
__device__ float g_base[BB*NN*H1];
__device__ float g_xw3[BB*NN*OUTD];

__device__ __forceinline__ float leaky(float v) { return v >= 0.f ? v : SLOPE * v; }

// ---------------------------------------------------------------------------
// Kernel 1: per-(b,j) precompute. Weights live in registers, not smem.
// ---------------------------------------------------------------------------
__global__ void __launch_bounds__(128) sgc_k1(
    const float* __restrict__ x, const float* __restrict__ adj,
    const float* __restrict__ W1, const float* __restrict__ b1,
    const float* __restrict__ W2, const float* __restrict__ b2,
    const float* __restrict__ W3, const float* __restrict__ b3)
{
    const int bj = blockIdx.x;
    const int b = bj / NN, j = bj % NN;
    const int tid = threadIdx.x;

    __shared__ float xb[NN*17];
    __shared__ float adjrow[NN];
    __shared__ float disrow[NN];
    __shared__ float s[DD];
    __shared__ float red[2];

    // ---- Front epoch: x, adj row, per-role weight columns into registers ----
    float Wa[DD], Wb[DD], Wc[DD], wjk = 0.f, b1v = 0.f;   // tid < 50
    float W2r[33], b2v = 0.f;                              // 64 <= tid < 114
    float W3r[DD], b3v = 0.f;                              // 64 <= tid < 128

    if (tid < H0) {
        #pragma unroll
        for (int d = 0; d < DD; d++) {
            Wa[d] = W1[d*H0 + tid];
            Wb[d] = W1[(DD + d)*H0 + tid];
            Wc[d] = W1[(2*DD + d)*H0 + tid];
        }
        wjk = W1[(3*DD + 1)*H0 + tid];
        b1v = b1[tid];
    }
    if (tid >= 64 && tid < 64 + H1) {
        #pragma unroll
        for (int r = 0; r < 33; r++) W2r[r] = W2[r*H1 + (tid - 64)];
        b2v = b2[tid - 64];
    }
    if (tid >= 64) {
        #pragma unroll
        for (int d = 0; d < DD; d++) W3r[d] = W3[d*OUTD + (tid - 64)];
        b3v = b3[tid - 64];
    }
    {
        const float4* xv = (const float4*)(x + b*NN*DD);
        #pragma unroll
        for (int idx = tid; idx < NN*DD/4; idx += 128) {
            float4 v = xv[idx];
            const int base = (idx >> 2)*17 + (idx & 3)*4;
            xb[base] = v.x; xb[base+1] = v.y; xb[base+2] = v.z; xb[base+3] = v.w;
        }
    }
    if (tid < NN) adjrow[tid] = adj[(b*NN + j)*NN + tid];
    __syncthreads();

    // ---- Phase 2: dis row j ; g_xw3 (independent of dis) ----
    if (tid < NN) {
        float d2 = 1e-10f;
        #pragma unroll
        for (int d = 0; d < DD; d++) {
            const float df = xb[j*17 + d] - xb[tid*17 + d];
            d2 += df * df;
        }
        disrow[tid] = sqrtf(d2);
    }
    if (tid >= 64) {
        float acc = b3v;
        #pragma unroll
        for (int d = 0; d < DD; d++) acc = fmaf(xb[j*17 + d], W3r[d], acc);
        g_xw3[bj*OUTD + (tid - 64)] = acc;
    }
    __syncthreads();

    // ---- Phase 3: reductions ----
    if (tid < 32) {
        float dg = 0.f, sd = 0.f;
        #pragma unroll
        for (int k = tid; k < NN; k += 32) {
            const float a = adjrow[k];
            dg += a; sd += a * disrow[k];
        }
        #pragma unroll
        for (int o = 16; o; o >>= 1) {
            dg += __shfl_down_sync(~0u, dg, o);
            sd += __shfl_down_sync(~0u, sd, o);
        }
        if (tid == 0) { red[0] = dg; red[1] = sd; g_deg[bj] = dg; }
    }
    if (tid >= 32 && tid < 32 + DD) {
        const int d = tid - 32;
        float acc = 0.f;
        #pragma unroll 4
        for (int k = 0; k < NN; k++) acc += adjrow[k] * xb[k*17 + d];
        s[d] = acc;
    }
    __syncthreads();

    // ---- Phase 4: A/P (regs) and g_base (regs) ----
    if (tid < H0) {
        float Av = 0.f, Bv = 0.f, Cv = 0.f;
        #pragma unroll
        for (int d = 0; d < DD; d++) {
            const float xv = xb[j*17 + d];
            Av = fmaf(xv,  Wa[d], Av);
            Bv = fmaf(xv,  Wb[d], Bv);
            Cv = fmaf(s[d], Wc[d], Cv);
        }
        g_A[bj*H0 + tid] = Av;
        g_P[bj*H0 + tid] = red[0]*(Bv + b1v) + Cv + red[1]*wjk;
    } else if (tid >= 64 && tid < 64 + H1) {
        const float dg = red[0];
        float acc = dg * b2v;
        #pragma unroll
        for (int d = 0; d < DD; d++) {
            acc = fmaf(dg * xb[j*17 + d], W2r[d], acc);
            acc = fmaf(s[d],              W2r[DD + d], acc);
        }
        acc = fmaf(red[1], W2r[2*DD], acc);
        g_base[bj*H1 + (tid - 64)] = acc;
    }
}

// ---------------------------------------------------------------------------
// Kernel 2: per-(b,i). W2d/W3b columns in registers; Pst chunked staging.
// ---------------------------------------------------------------------------
__global__ void __launch_bounds__(128) sgc_k2(
    const float* __restrict__ x, const float* __restrict__ adj,
    const float* __restrict__ W1,
    const float* __restrict__ W2,
    const float* __restrict__ W3,
    float* __restrict__ out)
{
    const int bi = blockIdx.x;
    const int b = bi / NN, i = bi % NN;
    const int tid = threadIdx.x;

    __shared__ float xb[NN*17];
    __shared__ float Pst[CHUNK*H0];
    __shared__ float dis_i[NN];
    __shared__ float sdik[NN];
    __shared__ float ddeg[NN];
    __shared__ float ddij[NN];
    __shared__ float taccS[H0], m2s[H1];
    __shared__ int   nz[NN];
    __shared__ int   wcnt[3];
    __shared__ int   nnzS;

    // ---- Front epoch ----
    float wreg[H0];            // tid<50: W2d column; tid>=64: W3b column
    float Ah = 0.f, wij = 0.f, wik = 0.f, base2 = 0.f, xw3 = 0.f;

    if (tid < H0) {
        #pragma unroll
        for (int h = 0; h < H0; h++) wreg[h] = W2[(2*DD + 1 + h)*H1 + tid];
        Ah    = g_A[bi*H0 + tid];
        base2 = g_base[bi*H1 + tid];
        wij   = W1[(3*DD + 0)*H0 + tid];
        wik   = W1[(3*DD + 2)*H0 + tid];
    } else if (tid >= 64) {
        #pragma unroll
        for (int h = 0; h < H1; h++) wreg[h] = W3[(DD + h)*OUTD + (tid - 64)];
        xw3 = g_xw3[bi*OUTD + (tid - 64)];
    }
    {
        const float4* xv = (const float4*)(x + b*NN*DD);
        #pragma unroll
        for (int idx = tid; idx < NN*DD/4; idx += 128) {
            float4 v = xv[idx];
            const int base = (idx >> 2)*17 + (idx & 3)*4;
            xb[base] = v.x; xb[base+1] = v.y; xb[base+2] = v.z; xb[base+3] = v.w;
        }
    }
    float adjv = 0.f;
    if (tid < NN) adjv = adj[(b*NN + i)*NN + tid];
    __syncthreads();

    // ---- Phase B: dis_i + compaction ----
    bool nzb = false; unsigned mk = 0u;
    if (tid < NN) {
        float d2 = 1e-10f;
        #pragma unroll
        for (int d = 0; d < DD; d++) {
            const float df = xb[i*17 + d] - xb[tid*17 + d];
            d2 += df * df;
        }
        dis_i[tid] = sqrtf(d2);
        nzb = (adjv != 0.f);
        mk = __ballot_sync(~0u, nzb);
        if ((tid & 31) == 0) wcnt[tid >> 5] = __popc(mk);
    }
    __syncthreads();
    if (tid < NN && nzb) {
        const int w = tid >> 5, lane = tid & 31;
        int off = __popc(mk & ((1u << lane) - 1u));
        #pragma unroll
        for (int u = 0; u < 3; u++) if (u < w) off += wcnt[u];
        nz[off] = tid;
    }
    if (tid == 0) nnzS = wcnt[0] + wcnt[1] + wcnt[2];
    __syncthreads();

    const int nnz = nnzS;

    // ---- Phase C: per-m scalars + sd_ik (dependent epoch) ----
    if (tid < nnz) {
        const float dg = g_deg[b*NN + nz[tid]];
        ddeg[tid] = dg;
        ddij[tid] = dg * dis_i[nz[tid]];
    }
    {
        const int w = tid >> 5, lane = tid & 31;
        for (int m = w; m < nnz; m += 4) {
            const float* row = adj + (b*NN + nz[m])*NN;
            float v = row[lane]    * dis_i[lane]
                    + row[lane+32] * dis_i[lane+32]
                    + row[lane+64] * dis_i[lane+64];
            #pragma unroll
            for (int o = 16; o; o >>= 1) v += __shfl_down_sync(~0u, v, o);
            if (lane == 0) sdik[m] = v;
        }
    }
    __syncthreads();

    // ---- Phase D: t[h], chunked P staging ----
    float accD = 0.f;
    for (int c0 = 0; c0 < nnz; c0 += CHUNK) {
        const int cn = min(nnz - c0, CHUNK);
        for (int idx = tid; idx < cn*(H0/2); idx += 128) {
            const int m = idx / (H0/2), q = idx % (H0/2);
            ((float2*)Pst)[m*(H0/2) + q] =
                ((const float2*)(g_P + (b*NN + nz[c0+m])*H0))[q];
        }
        __syncthreads();
        if (tid < H0) {
            #pragma unroll 4
            for (int m = 0; m < cn; m++) {
                const float Sv = fmaf(ddeg[c0+m], Ah,
                                 fmaf(ddij[c0+m], wij,
                                 fmaf(sdik[c0+m], wik, Pst[m*H0 + tid])));
                accD += leaky(Sv);
            }
        }
        __syncthreads();
    }
    if (tid < H0) taccS[tid] = accD;
    __syncthreads();

    // ---- Phase E (tid<50): m2 from registers ----
    if (tid < H1) {
        float acc = base2;
        #pragma unroll
        for (int h = 0; h < H0; h++) acc = fmaf(taccS[h], wreg[h], acc);
        m2s[tid] = leaky(acc);
    }
    __syncthreads();

    // ---- Phase F (tid>=64): out from registers ----
    if (tid >= 64) {
        float acc = xw3;
        #pragma unroll
        for (int h = 0; h < H1; h++) acc = fmaf(m2s[h], wreg[h], acc);
        out[bi*OUTD + (tid - 64)] = leaky(acc);
    }
}

extern "C" void kernel_launch(void* const* d_in, const int* in_sizes, int n_in,
                              void* d_out, int out_size)
{
    const float* x   = (const float*)d_in[0];
    const float* adj = (const float*)d_in[1];
    const float* W1  = (const float*)d_in[2];
    const float* b1  = (const float*)d_in[3];
    const float* W2  = (const float*)d_in[4];
    const float* b2  = (const float*)d_in[5];
    const float* W3  = (const float*)d_in[6];
    const float* b3  = (const float*)d_in[7];
    float* out = (float*)d_out;

    sgc_k1<<<BB*NN, 128>>>(x, adj, W1, b1, W2, b2, W3, b3);
    sgc_k2<<<BB*NN, 128>>>(x, adj, W1, W2, W3, out);
}

// round 9
// speedup vs baseline: 2.6291x; 1.1648x over previous
#include <cuda_runtime.h>
#include <cuda_bf16.h>
#include <math.h>

#define BB 8
#define NN 96
#define DD 16
#define H0 50
#define H1 50
#define OUTD 64
#define SLOPE 0.05f
#define GRID (BB*NN/2)     // 384 blocks, all co-resident (>=3/SM via launch_bounds)
#define NTH 256
#define CH 12

__device__ unsigned long long g_bar;      // monotonic ticket barrier (never reset)
__device__ float g_P[BB*NN*H0];           // only cross-block datum

struct Sm {
    float xb[NN*17];          // float4-loaded (offset 0)
    float W3s[H1*OUTD];       // W3 rows 16..65 (float4 staged; offset 6528B, 16B-aligned)
    float W1s[51*H0];         // all W1 (float2 staged)
    float W2s[H0*H1];         // W2 rows 33..82 (float2 staged)
    float b1s[H0], b2s[H1], b3s[OUTD];
    float disR[2*NN];
    float sdik[2*NN], degJ[2*NN], ddij[2*NN];
    float adjx[2*DD];
    float A_R[2*H0], base2[2*H0], xw3[2*OUTD];
    float Pst[2*CH*H0];       // float2 staged; preceding float count even -> 8B aligned
    float tacc[2*H0], m2S[2*H1];
    float sdjk[2];
    int   nnzA[2], wcnt[6];
    unsigned char nzI[2*NN];
};

__device__ __forceinline__ float leaky(float v) { return v >= 0.f ? v : SLOPE * v; }

__global__ void __launch_bounds__(NTH, 3) sgc_fused(
    const float* __restrict__ x, const float* __restrict__ adj,
    const float* __restrict__ W1, const float* __restrict__ b1,
    const float* __restrict__ W2, const float* __restrict__ b2,
    const float* __restrict__ W3, const float* __restrict__ b3,
    float* __restrict__ out)
{
    extern __shared__ unsigned char raw[];
    Sm& S = *(Sm*)raw;
    const int tid = threadIdx.x;
    const int w = tid >> 5, lane = tid & 31;
    const int b  = blockIdx.x / (NN/2);
    const int r0 = (blockIdx.x % (NN/2)) * 2;   // block owns rows r0, r0+1 (as both j and i)

    // ===== Phase 0: front-batched independent staging =====
    {
        const float4* xv = (const float4*)(x + b*NN*DD);
        #pragma unroll
        for (int idx = tid; idx < NN*DD/4; idx += NTH) {
            float4 v = xv[idx];
            const int base = (idx >> 2)*17 + (idx & 3)*4;
            S.xb[base] = v.x; S.xb[base+1] = v.y; S.xb[base+2] = v.z; S.xb[base+3] = v.w;
        }
        const float4* w3v = (const float4*)(W3 + DD*OUTD);
        #pragma unroll
        for (int idx = tid; idx < H1*OUTD/4; idx += NTH) ((float4*)S.W3s)[idx] = w3v[idx];
        const float2* w1v = (const float2*)W1;
        #pragma unroll
        for (int idx = tid; idx < 51*H0/2; idx += NTH) ((float2*)S.W1s)[idx] = w1v[idx];
        const float2* w2v = (const float2*)(W2 + (2*DD+1)*H1);
        #pragma unroll
        for (int idx = tid; idx < H0*H1/2; idx += NTH) ((float2*)S.W2s)[idx] = w2v[idx];
        if (tid < H0) S.b1s[tid] = b1[tid];
        else if (tid < H0+H1) S.b2s[tid-H0] = b2[tid-H0];
        else if (tid < H0+H1+OUTD) S.b3s[tid-H0-H1] = b3[tid-H0-H1];
    }
    __syncthreads();

    // ===== Phase 1: dis rows (both), adj compaction (threads 0..191) =====
    bool nzb = false; unsigned mk = 0u; int kk = 0, iiq = 0;
    if (tid < 2*NN) {
        iiq = (w >= 3);                 // warps 0..2 -> ii=0, 3..5 -> ii=1
        kk = (w - iiq*3)*32 + lane;
        const int r = r0 + iiq;
        float d2 = 1e-10f;
        #pragma unroll
        for (int d = 0; d < DD; d++) { const float df = S.xb[r*17+d] - S.xb[kk*17+d]; d2 += df*df; }
        S.disR[iiq*NN + kk] = sqrtf(d2);
        const float av = adj[(b*NN + r)*NN + kk];
        nzb = (av != 0.f);
        mk = __ballot_sync(~0u, nzb);
        if (lane == 0) S.wcnt[w] = __popc(mk);
    }
    __syncthreads();
    if (tid < 2*NN && nzb) {
        const int seg = w - iiq*3;
        int off = __popc(mk & ((1u << lane) - 1u));
        #pragma unroll
        for (int u = 0; u < 3; u++) if (u < seg) off += S.wcnt[iiq*3 + u];
        S.nzI[iiq*NN + off] = (unsigned char)kk;
    }
    if (tid < 2) S.nnzA[tid] = S.wcnt[tid*3] + S.wcnt[tid*3+1] + S.wcnt[tid*3+2];
    __syncthreads();

    const int nnz0 = S.nnzA[0], nnz1 = S.nnzA[1];

    // ===== Phase 2: neighbor rows (warps 0..5); adjx/sdjk/xw3 (warps 6..7) =====
    if (w < 6) {
        const int totp = nnz0 + nnz1;
        for (int p = w; p < totp; p += 6) {
            const int ii = (p >= nnz0);
            const int m  = ii ? p - nnz0 : p;
            const int j  = S.nzI[ii*NN + m];
            const float* row = adj + (b*NN + j)*NN;
            const float* dis = S.disR + ii*NN;
            const float a0 = row[lane], a1 = row[lane+32], a2 = row[lane+64];
            const int cnt = __popc(__ballot_sync(~0u, a0 != 0.f))
                          + __popc(__ballot_sync(~0u, a1 != 0.f))
                          + __popc(__ballot_sync(~0u, a2 != 0.f));
            float v = a0*dis[lane] + a1*dis[lane+32] + a2*dis[lane+64];
            #pragma unroll
            for (int o = 16; o; o >>= 1) v += __shfl_down_sync(~0u, v, o);
            if (lane == 0) {
                S.sdik[ii*NN + m] = v;
                const float dgj = (float)cnt;
                S.degJ[ii*NN + m] = dgj;
                S.ddij[ii*NN + m] = dgj * dis[j];
            }
        }
    } else {
        const int idx = tid - 192;     // 0..63
        if (idx < 2*DD) {              // adjx
            const int ii = idx / DD, d = idx % DD;
            const int nn = ii ? nnz1 : nnz0;
            float acc = 0.f;
            for (int m = 0; m < nn; m++) acc += S.xb[S.nzI[ii*NN + m]*17 + d];
            S.adjx[idx] = acc;
        } else if (idx < 2*DD + 2) {   // sdjk (own rows: = sum of own dis over nz)
            const int ii = idx - 2*DD;
            const int nn = ii ? nnz1 : nnz0;
            float acc = 0.f;
            for (int m = 0; m < nn; m++) acc += S.disR[ii*NN + S.nzI[ii*NN + m]];
            S.sdjk[ii] = acc;
        }
        for (int q = idx; q < 2*OUTD; q += 64) {   // xw3 (W3 rows 0..15 direct)
            const int ii = q >> 6, o = q & 63;
            float acc = S.b3s[o];
            #pragma unroll
            for (int d = 0; d < DD; d++) acc = fmaf(S.xb[(r0+ii)*17+d], W3[d*OUTD + o], acc);
            S.xw3[q] = acc;
        }
    }
    __syncthreads();

    // ===== Phase 3: A/P (t<100), base2 (100<=t<200) =====
    if (tid < 2*H0) {
        const int ii = tid / H0, h = tid % H0;
        const int j = r0 + ii;
        float Av = 0.f, Bv = 0.f, Cv = 0.f;
        #pragma unroll
        for (int d = 0; d < DD; d++) {
            const float xv = S.xb[j*17 + d];
            Av = fmaf(xv, S.W1s[d*H0 + h], Av);
            Bv = fmaf(xv, S.W1s[(DD + d)*H0 + h], Bv);
            Cv = fmaf(S.adjx[ii*DD + d], S.W1s[(2*DD + d)*H0 + h], Cv);
        }
        S.A_R[tid] = Av;
        const float dg = (float)(ii ? nnz1 : nnz0);
        g_P[(b*NN + j)*H0 + h] =
            dg*(Bv + S.b1s[h]) + Cv + S.sdjk[ii]*S.W1s[(3*DD + 1)*H0 + h];
    } else if (tid < 4*H0) {
        const int idx = tid - 2*H0, ii = idx / H1, h1 = idx % H1;
        const int i = r0 + ii;
        const float dgi = (float)(ii ? nnz1 : nnz0);
        float acc = dgi * S.b2s[h1];
        #pragma unroll
        for (int d = 0; d < DD; d++) {
            acc = fmaf(dgi * S.xb[i*17+d], W2[d*H1 + h1], acc);
            acc = fmaf(S.adjx[ii*DD + d], W2[(DD + d)*H1 + h1], acc);
        }
        acc = fmaf(S.sdjk[ii], W2[(2*DD)*H1 + h1], acc);
        S.base2[idx] = acc;
    }
    __syncthreads();

    // ===== Grid barrier (monotonic ticket; all 384 blocks co-resident) =====
    if (tid == 0) {
        __threadfence();
        const unsigned long long t = atomicAdd(&g_bar, 1ULL);
        const unsigned long long target = t - (t % GRID) + GRID;
        while (*(volatile unsigned long long*)&g_bar < target) __nanosleep(20);
        __threadfence();
    }
    __syncthreads();

    // ===== Phase D: t[h] over neighbors, chunked __ldcg P staging =====
    float accD = 0.f;
    const int mx = max(nnz0, nnz1);
    for (int c0 = 0; c0 < mx; c0 += CH) {
        for (int idx = tid; idx < 2*CH*(H0/2); idx += NTH) {
            const int ii = idx / (CH*(H0/2));
            const int rem = idx % (CH*(H0/2));
            const int m = rem / (H0/2), q = rem % (H0/2);
            if (c0 + m < (ii ? nnz1 : nnz0)) {
                const int j = S.nzI[ii*NN + c0 + m];
                ((float2*)S.Pst)[ii*CH*(H0/2) + m*(H0/2) + q] =
                    __ldcg((const float2*)(g_P + (b*NN + j)*H0) + q);
            }
        }
        __syncthreads();
        if (tid < 2*H0) {
            const int ii = tid / H0, h = tid % H0;
            const float Ah  = S.A_R[tid];
            const float wij = S.W1s[(3*DD)*H0 + h];
            const float wik = S.W1s[(3*DD + 2)*H0 + h];
            const int lim = min((ii ? nnz1 : nnz0) - c0, CH);
            for (int m = 0; m < lim; m++) {
                const int pm = ii*NN + c0 + m;
                const float Sv = fmaf(S.degJ[pm], Ah,
                                 fmaf(S.ddij[pm], wij,
                                 fmaf(S.sdik[pm], wik, S.Pst[(ii*CH + m)*H0 + h])));
                accD += leaky(Sv);
            }
        }
        __syncthreads();
    }
    if (tid < 2*H0) S.tacc[tid] = accD;
    __syncthreads();

    // ===== Phase E: m2 (smem) =====
    if (tid < 2*H1) {
        const int ii = tid / H1, h1 = tid % H1;
        float acc = S.base2[tid];
        #pragma unroll 10
        for (int h = 0; h < H0; h++)
            acc = fmaf(S.tacc[ii*H0 + h], S.W2s[h*H1 + h1], acc);
        S.m2S[tid] = leaky(acc);
    }
    __syncthreads();

    // ===== Phase F: out (smem) =====
    if (tid < 2*OUTD) {
        const int ii = tid / OUTD, o = tid % OUTD;
        float acc = S.xw3[tid];
        #pragma unroll 10
        for (int h = 0; h < H1; h++)
            acc = fmaf(S.m2S[ii*H1 + h], S.W3s[h*OUTD + o], acc);
        out[(b*NN + r0 + ii)*OUTD + o] = leaky(acc);
    }
}

extern "C" void kernel_launch(void* const* d_in, const int* in_sizes, int n_in,
                              void* d_out, int out_size)
{
    const float* x   = (const float*)d_in[0];
    const float* adj = (const float*)d_in[1];
    const float* W1  = (const float*)d_in[2];
    const float* b1  = (const float*)d_in[3];
    const float* W2  = (const float*)d_in[4];
    const float* b2  = (const float*)d_in[5];
    const float* W3  = (const float*)d_in[6];
    const float* b3  = (const float*)d_in[7];
    float* out = (float*)d_out;

    cudaFuncSetAttribute(sgc_fused,
        cudaFuncAttributeMaxDynamicSharedMemorySize, (int)sizeof(Sm));
    sgc_fused<<<GRID, NTH, sizeof(Sm)>>>(x, adj, W1, b1, W2, b2, W3, b3, out);
}

// round 11
// speedup vs baseline: 3.6388x; 1.3840x over previous
#include <cuda_runtime.h>
#include <cuda_bf16.h>
#include <math.h>

#define BB 8
#define NN 96
#define DD 16
#define H0 50
#define H1 50
#define OUTD 64
#define SLOPE 0.05f
#define CH 32

// Scratch (__device__ globals; allocation-free)
__device__ float g_A[BB*NN*H0];
__device__ float g_P[BB*NN*H0];
__device__ float g_deg[BB*NN];
__device__ float g_base[BB*NN*H1];
__device__ float g_xw3[BB*NN*OUTD];

__device__ __forceinline__ float leaky(float v) { return v >= 0.f ? v : SLOPE * v; }

// ---------------------------------------------------------------------------
// Kernel 1: per-(b,j) precompute (unchanged from R3 champion).
// ---------------------------------------------------------------------------
__global__ void __launch_bounds__(128) sgc_k1(
    const float* __restrict__ x, const float* __restrict__ adj,
    const float* __restrict__ W1, const float* __restrict__ b1,
    const float* __restrict__ W2, const float* __restrict__ b2,
    const float* __restrict__ W3, const float* __restrict__ b3)
{
    const int bj = blockIdx.x;
    const int b = bj / NN, j = bj % NN;
    const int tid = threadIdx.x;

    __shared__ float xb[NN*17];
    __shared__ float W1s[51*H0];
    __shared__ float W2s[33*H1];
    __shared__ float W3s[DD*OUTD];
    __shared__ float b1s[H0], b2s[H1], b3s[OUTD];
    __shared__ float adjrow[NN];
    __shared__ float disrow[NN];
    __shared__ float s[DD];
    __shared__ float red[2];

    {
        const float4* xB4 = (const float4*)(x + b*NN*DD);
        #pragma unroll
        for (int idx = tid; idx < NN*DD/4; idx += 128) {
            float4 v = xB4[idx];
            const int base = (idx >> 2)*17 + (idx & 3)*4;
            xb[base+0] = v.x; xb[base+1] = v.y; xb[base+2] = v.z; xb[base+3] = v.w;
        }
        const float2* W1v = (const float2*)W1;
        #pragma unroll
        for (int idx = tid; idx < 51*H0/2; idx += 128) ((float2*)W1s)[idx] = W1v[idx];
        const float2* W2v = (const float2*)W2;
        #pragma unroll
        for (int idx = tid; idx < 33*H1/2; idx += 128) ((float2*)W2s)[idx] = W2v[idx];
        const float4* W3v = (const float4*)W3;
        #pragma unroll
        for (int idx = tid; idx < DD*OUTD/4; idx += 128) ((float4*)W3s)[idx] = W3v[idx];
        if (tid < NN)   adjrow[tid] = adj[(b*NN + j)*NN + tid];
        if (tid < H0)   b1s[tid] = b1[tid];
        if (tid < H1)   b2s[tid] = b2[tid];
        if (tid < OUTD) b3s[tid] = b3[tid];
    }
    __syncthreads();

    if (tid < NN) {
        float d2 = 1e-10f;
        #pragma unroll
        for (int d = 0; d < DD; d++) {
            const float df = xb[j*17 + d] - xb[tid*17 + d];
            d2 += df * df;
        }
        disrow[tid] = sqrtf(d2);
    }
    __syncthreads();

    if (tid < 32) {
        float dg = 0.f, sd = 0.f;
        #pragma unroll
        for (int k = tid; k < NN; k += 32) {
            const float a = adjrow[k];
            dg += a; sd += a * disrow[k];
        }
        #pragma unroll
        for (int o = 16; o; o >>= 1) {
            dg += __shfl_down_sync(0xffffffffu, dg, o);
            sd += __shfl_down_sync(0xffffffffu, sd, o);
        }
        if (tid == 0) { red[0] = dg; red[1] = sd; g_deg[bj] = dg; }
    }
    if (tid >= 32 && tid < 32 + DD) {
        const int d = tid - 32;
        float acc = 0.f;
        #pragma unroll 4
        for (int k = 0; k < NN; k++) acc += adjrow[k] * xb[k*17 + d];
        s[d] = acc;
    }
    if (tid >= 64) {
        const int o = tid - 64;
        float acc = b3s[o];
        #pragma unroll
        for (int d = 0; d < DD; d++) acc += xb[j*17 + d] * W3s[d*OUTD + o];
        g_xw3[bj*OUTD + o] = acc;
    }
    __syncthreads();

    if (tid < H0) {
        const int h = tid;
        float Av = 0.f, Bv = 0.f, Cv = 0.f;
        #pragma unroll
        for (int d = 0; d < DD; d++) {
            const float xv = xb[j*17 + d];
            Av += xv   * W1s[d*H0 + h];
            Bv += xv   * W1s[(DD + d)*H0 + h];
            Cv += s[d] * W1s[(2*DD + d)*H0 + h];
        }
        g_A[bj*H0 + h] = Av;
        g_P[bj*H0 + h] = red[0]*(Bv + b1s[h]) + Cv + red[1] * W1s[(3*DD + 1)*H0 + h];
    } else if (tid >= 64 && tid < 64 + H1) {
        const int h1 = tid - 64;
        const float dg = red[0];
        float acc = dg * b2s[h1];
        #pragma unroll
        for (int d = 0; d < DD; d++) {
            acc += dg * xb[j*17 + d] * W2s[d*H1 + h1];
            acc += s[d]              * W2s[(DD + d)*H1 + h1];
        }
        acc += red[1] * W2s[(2*DD)*H1 + h1];
        g_base[bj*H1 + h1] = acc;
    }
}

// ---------------------------------------------------------------------------
// Kernel 2: per-(b,i). Single merged dependent epoch (adj rows + P + deg).
// ---------------------------------------------------------------------------
__global__ void __launch_bounds__(128) sgc_k2(
    const float* __restrict__ x, const float* __restrict__ adj,
    const float* __restrict__ W1,
    const float* __restrict__ W2,
    const float* __restrict__ W3,
    float* __restrict__ out)
{
    const int bi = blockIdx.x;
    const int b = bi / NN, i = bi % NN;
    const int tid = threadIdx.x;

    __shared__ __align__(16) float xb[NN*17];
    __shared__ __align__(16) float W2s[H0*H1];     // W2 rows 33..82
    __shared__ __align__(16) float W3s[H1*OUTD];   // W3 rows 16..65
    __shared__ __align__(8)  float Pst[CH*H0];
    __shared__ float dis_i[NN];
    __shared__ float sdik[CH], ddeg[CH], ddij[CH];
    __shared__ float taccS[H0], m2s[H1];
    __shared__ int   nz[NN];
    __shared__ int   wcnt[3];
    __shared__ int   nnzS;

    // ---- Front epoch: everything address-independent ----
    float Ah = 0.f, wij = 0.f, wik = 0.f, base2 = 0.f, xw3 = 0.f;
    {
        const float4* xv = (const float4*)(x + b*NN*DD);
        #pragma unroll
        for (int idx = tid; idx < NN*DD/4; idx += 128) {
            float4 v = xv[idx];
            const int base = (idx >> 2)*17 + (idx & 3)*4;
            xb[base] = v.x; xb[base+1] = v.y; xb[base+2] = v.z; xb[base+3] = v.w;
        }
        const float2* w2v = (const float2*)(W2 + (2*DD + 1)*H1);
        #pragma unroll
        for (int idx = tid; idx < H0*H1/2; idx += 128) ((float2*)W2s)[idx] = w2v[idx];
        const float4* w3v = (const float4*)(W3 + DD*OUTD);
        #pragma unroll
        for (int idx = tid; idx < H1*OUTD/4; idx += 128) ((float4*)W3s)[idx] = w3v[idx];
        if (tid < H0) {
            Ah    = g_A[bi*H0 + tid];
            base2 = g_base[bi*H1 + tid];
            wij   = W1[(3*DD + 0)*H0 + tid];
            wik   = W1[(3*DD + 2)*H0 + tid];
        } else if (tid >= 64) {
            xw3 = g_xw3[bi*OUTD + (tid - 64)];
        }
    }
    float adjv = 0.f;
    if (tid < NN) adjv = adj[(b*NN + i)*NN + tid];
    __syncthreads();

    // ---- dis_i + nz compaction ----
    bool nzb = false; unsigned mk = 0u;
    if (tid < NN) {
        float d2 = 1e-10f;
        #pragma unroll
        for (int d = 0; d < DD; d++) {
            const float df = xb[i*17 + d] - xb[tid*17 + d];
            d2 += df * df;
        }
        dis_i[tid] = sqrtf(d2);
        nzb = (adjv != 0.f);
        mk = __ballot_sync(~0u, nzb);
        if ((tid & 31) == 0) wcnt[tid >> 5] = __popc(mk);
    }
    __syncthreads();
    if (tid < NN && nzb) {
        const int w = tid >> 5, lane = tid & 31;
        int off = __popc(mk & ((1u << lane) - 1u));
        #pragma unroll
        for (int u = 0; u < 3; u++) if (u < w) off += wcnt[u];
        nz[off] = tid;
    }
    if (tid == 0) nnzS = wcnt[0] + wcnt[1] + wcnt[2];
    __syncthreads();

    const int nnz = nnzS;

    // ---- Chunked merged epoch + t accumulation ----
    float accD = 0.f;
    const int mq = tid >> 2, sub = tid & 3;   // 4 threads per neighbor row slot
    for (int c0 = 0; c0 < nnz; c0 += CH) {
        const int cn = min(nnz - c0, CH);

        // (a) adj row partials: 4 threads/row, 6 float4 each (all in flight)
        float v = 0.f;
        if (mq < cn) {
            const int j = nz[c0 + mq];
            const float4* row4 = (const float4*)(adj + (b*NN + j)*NN) + sub*6;
            #pragma unroll
            for (int q = 0; q < 6; q++) {
                const float4 a = row4[q];
                const int kb = sub*24 + q*4;
                v += a.x*dis_i[kb] + a.y*dis_i[kb+1] + a.z*dis_i[kb+2] + a.w*dis_i[kb+3];
            }
        }
        // (b) P rows (independent of (a))
        for (int idx = tid; idx < cn*(H0/2); idx += 128) {
            const int m = idx / (H0/2), q = idx % (H0/2);
            ((float2*)Pst)[m*(H0/2) + q] =
                ((const float2*)(g_P + (b*NN + nz[c0+m])*H0))[q];
        }
        // (c) deg (independent)
        if (tid < cn) {
            const float dg = g_deg[b*NN + nz[c0+tid]];
            ddeg[tid] = dg;
            ddij[tid] = dg * dis_i[nz[c0+tid]];
        }
        // quad reduce for sd_ik
        v += __shfl_xor_sync(~0u, v, 1);
        v += __shfl_xor_sync(~0u, v, 2);
        if (sub == 0 && mq < cn) sdik[mq] = v;
        __syncthreads();

        if (tid < H0) {
            #pragma unroll 4
            for (int m = 0; m < cn; m++) {
                const float Sv = fmaf(ddeg[m], Ah,
                                 fmaf(ddij[m], wij,
                                 fmaf(sdik[m], wik, Pst[m*H0 + tid])));
                accD += leaky(Sv);
            }
        }
        __syncthreads();
    }
    if (tid < H0) taccS[tid] = accD;
    __syncthreads();

    // ---- E: m2 (smem) ----
    if (tid < H1) {
        float acc = base2;
        #pragma unroll 10
        for (int h = 0; h < H0; h++)
            acc = fmaf(taccS[h], W2s[h*H1 + tid], acc);
        m2s[tid] = leaky(acc);
    }
    __syncthreads();

    // ---- F: out (smem) ----
    if (tid >= 64) {
        const int o = tid - 64;
        float acc = xw3;
        #pragma unroll 10
        for (int h = 0; h < H1; h++)
            acc = fmaf(m2s[h], W3s[h*OUTD + o], acc);
        out[bi*OUTD + o] = leaky(acc);
    }
}

extern "C" void kernel_launch(void* const* d_in, const int* in_sizes, int n_in,
                              void* d_out, int out_size)
{
    const float* x   = (const float*)d_in[0];
    const float* adj = (const float*)d_in[1];
    const float* W1  = (const float*)d_in[2];
    const float* b1  = (const float*)d_in[3];
    const float* W2  = (const float*)d_in[4];
    const float* b2  = (const float*)d_in[5];
    const float* W3  = (const float*)d_in[6];
    const float* b3  = (const float*)d_in[7];
    float* out = (float*)d_out;

    sgc_k1<<<BB*NN, 128>>>(x, adj, W1, b1, W2, b2, W3, b3);
    sgc_k2<<<BB*NN, 128>>>(x, adj, W1, W2, W3, out);
}